// round 12
// baseline (speedup 1.0000x reference)
#include <cuda_runtime.h>
#include <math.h>

// DDSL spec: B=2, NV=NE=512, RES=(128,128) -> freq grid 128 x 65, J=2.
// Direct packed kernel: two adjacent fx freqs (kx,kx+1) per thread via f32x2.
// One full warp per freq-pair (32 lanes x 16 edges) -> 8320 warps for issue
// occupancy; each lane's 16 edges split into TWO independent 8-edge ring
// chains (ILP). Ring reuse: 1 vertex sincos per edge. Single product-rcp
// divide (dlo sanitized; junk lands only in the DC slot, overwritten).

#define NV      512
#define NE      512
#define FX      128
#define FY2     65
#define NFP     (FX / 2 * FY2)      // 4160 fx-pairs
#define GROUPS  8                   // freq-pairs (warps) per block
#define BLOCK   256
#define EPC     8                   // edges per chain (2 chains per lane)
#define PADDED  529                 // pad(e)=e+(e>>5); pad(512)=528 wrap dup

typedef unsigned long long u64;

__device__ __forceinline__ u64 pk2(float a, float b) {
    u64 r; asm("mov.b64 %0, {%1, %2};" : "=l"(r) : "f"(a), "f"(b)); return r;
}
__device__ __forceinline__ void upk(u64 v, float& a, float& b) {
    asm("mov.b64 {%0, %1}, %2;" : "=f"(a), "=f"(b) : "l"(v));
}
__device__ __forceinline__ u64 f2fma(u64 a, u64 b, u64 c) {
    u64 d; asm("fma.rn.f32x2 %0, %1, %2, %3;" : "=l"(d) : "l"(a), "l"(b), "l"(c)); return d;
}
__device__ __forceinline__ u64 f2add(u64 a, u64 b) {
    u64 d; asm("add.rn.f32x2 %0, %1, %2;" : "=l"(d) : "l"(a), "l"(b)); return d;
}
__device__ __forceinline__ u64 f2mul(u64 a, u64 b) {
    u64 d; asm("mul.rn.f32x2 %0, %1, %2;" : "=l"(d) : "l"(a), "l"(b)); return d;
}

__device__ __forceinline__ float fracr(float t) {
    const float MAGIC = 12582912.0f;  // 1.5 * 2^23
    float g = __fadd_rn(t, MAGIC);
    float r = __fadd_rn(g, -MAGIC);
    return t - r;
}

__global__ __launch_bounds__(BLOCK, 4)
void ddsl_spec_kernel(const float* __restrict__ V,
                      const int*   __restrict__ E,
                      const float* __restrict__ D,
                      float*       __restrict__ out)
{
    __shared__ float sX[PADDED];
    __shared__ float sY[PADDED];
    __shared__ float sCD[PADDED];

    const int b = blockIdx.y;

    // ---- stage ring vertices + C*D ----
    for (int e = threadIdx.x; e < NE; e += BLOCK) {
        int i0 = E[(b * NE + e) * 2 + 0];
        int i1 = E[(b * NE + e) * 2 + 1];
        float ax = V[(b * NV + i0) * 2 + 0];
        float ay = V[(b * NV + i0) * 2 + 1];
        float bx = V[(b * NV + i1) * 2 + 0];
        float by = V[(b * NV + i1) * 2 + 1];
        int p = e + (e >> 5);
        sX[p] = ax;
        sY[p] = ay;
        sCD[p] = (ax * by - ay * bx) * D[b * NE + e];
        if (e == 0) { sX[528] = ax; sY[528] = ay; }   // ring wrap dup
    }
    __syncthreads();

    const int lane = threadIdx.x & 31;
    const int fp   = blockIdx.x * GROUPS + (threadIdx.x >> 5);

    const int fxp = fp / FY2;
    const int fy  = fp - fxp * FY2;
    const int fx0 = 2 * fxp;
    const int kx0 = (fx0 < FX / 2) ? fx0 : fx0 - FX;   // kx1 = kx0 + 1
    const float fkx = (float)kx0;
    const float fky = (float)fy;

    const float TWO_PI = 6.28318530717958647692f;
    const float MAGIC  = 12582912.0f;
    const u64 MAGIC2  = pk2(MAGIC, MAGIC);
    const u64 NMAGIC2 = pk2(-MAGIC, -MAGIC);
    const u64 NEG1    = pk2(-1.0f, -1.0f);
    const u64 TWOPI2  = pk2(TWO_PI, TWO_PI);

    // lane's 16-edge chunk: pad(16*lane + i) = 16*lane + (lane>>1) + i,
    // i = 0..15; final ring vertex offset = 16 + (lane & 1).
    const int base = 16 * lane + (lane >> 1);
    const float* xb = &sX[base];
    const float* yb = &sY[base];
    const float* cb = &sCD[base];
    const int lastoff = 16 + (lane & 1);

#define INITV(OFS, T, C, S)                                                \
    {                                                                      \
        float vx = xb[OFS], vy = yb[OFS];                                  \
        float tl = fmaf(vy, fky, vx * fkx);                                \
        float th = tl + vx;                                                \
        float sl, cl, sh, chh;                                             \
        __sincosf(fracr(tl) * TWO_PI, &sl, &cl);                           \
        __sincosf(fracr(th) * TWO_PI, &sh, &chh);                          \
        T = pk2(tl, th); C = pk2(cl, chh); S = pk2(sl, sh);                \
    }

#define STEP(T, C, S, OFS, CD, AR, AI)                                     \
    {                                                                      \
        float nx = xb[OFS], ny = yb[OFS];                                  \
        float cd = CD;                                                     \
        float t1lo = fmaf(ny, fky, nx * fkx);                              \
        u64 T1 = pk2(t1lo, t1lo + nx);                                     \
        u64 g  = f2add(T1, MAGIC2);                                        \
        u64 rr = f2add(g, NMAGIC2);                                        \
        u64 uu = f2fma(rr, NEG1, T1);                                      \
        u64 ph = f2mul(uu, TWOPI2);                                        \
        float plo, phi_, sl, cl, sh, chh;                                  \
        upk(ph, plo, phi_);                                                \
        __sincosf(plo, &sl, &cl);                                          \
        __sincosf(phi_, &sh, &chh);                                        \
        u64 SN1 = pk2(sl, sh), CS1 = pk2(cl, chh);                         \
        u64 dt  = f2fma(T1, NEG1, T);                                      \
        u64 den = f2mul(f2mul(T, T1), dt);                                 \
        u64 nt  = f2mul(T, NEG1);                                          \
        u64 nr  = f2fma(CS1, nt, f2fma(C, T1, dt));                        \
        u64 ni  = f2fma(SN1, nt, f2mul(S, T1));                            \
        float dlo, dhi; upk(den, dlo, dhi);                                \
        dlo = (dlo == 0.0f) ? 1.0f : dlo;                                  \
        float rp = __fdividef(cd, dlo * dhi);                              \
        u64 rc = pk2(rp * dhi, rp * dlo);                                  \
        AR = f2fma(nr, rc, AR);                                            \
        AI = f2fma(ni, rc, AI);                                            \
        T = T1; C = CS1; S = SN1;                                          \
    }

    u64 aR0 = pk2(0.0f, 0.0f), aI0 = pk2(0.0f, 0.0f);
    u64 aR1 = pk2(0.0f, 0.0f), aI1 = pk2(0.0f, 0.0f);

    u64 TA, CA, SA, TB, CB, SB;
    INITV(0, TA, CA, SA);      // chain A: edges 0..7 of chunk (verts 0..8)
    INITV(8, TB, CB, SB);      // chain B: edges 8..15 (verts 8..16/wrap)

#pragma unroll
    for (int i = 0; i < EPC; ++i) {
        const int offA = i + 1;                             // 1..8
        const int offB = (i == EPC - 1) ? lastoff : 9 + i;  // 9..15, then wrap
        STEP(TA, CA, SA, offA, cb[i],     aR0, aI0);
        STEP(TB, CB, SB, offB, cb[8 + i], aR1, aI1);
    }

    u64 accR = f2add(aR0, aR1);
    u64 accI = f2add(aI0, aI1);   // holds -Im

    // ---- reduce the 32 lanes (packed) ----
#pragma unroll
    for (int off = 16; off > 0; off >>= 1) {
        accR = f2add(accR, __shfl_down_sync(0xFFFFFFFFu, accR, off));
        accI = f2add(accI, __shfl_down_sync(0xFFFFFFFFu, accI, off));
    }

    if (lane == 0) {
        // F = -einsum * RES^J ; (2*pi)^-2 folded into SCALE. accI = -Im.
        const float SCALE = (float)(-16384.0 / (4.0 * 3.14159265358979323846
                                                    * 3.14159265358979323846));
        float aRlo, aRhi, aIlo, aIhi;
        upk(accR, aRlo, aRhi);
        upk(accI, aIlo, aIhi);
        float oRlo =  SCALE * aRlo, oRhi =  SCALE * aRhi;
        float oIlo = -SCALE * aIlo, oIhi = -SCALE * aIhi;

        if (fp == 0) {
            // DC: F[:,0,0,:,:] = 8192*sum(C*D) in BOTH re and im
            float s = 0.0f;
#pragma unroll 8
            for (int e = 0; e < NE; ++e) s += sCD[e + (e >> 5)];
            oRlo = 8192.0f * s;
            oIlo = oRlo;
        }

        int obase = ((b * FX + fx0) * FY2 + fy) * 2;
        out[obase + 0] = oRlo;
        out[obase + 1] = oIlo;
        out[obase + 2 * FY2 + 0] = oRhi;   // fx0 + 1
        out[obase + 2 * FY2 + 1] = oIhi;
    }
}

extern "C" void kernel_launch(void* const* d_in, const int* in_sizes, int n_in,
                              void* d_out, int out_size)
{
    const float* V = (const float*)d_in[0];
    const int*   E = (const int*)  d_in[1];
    const float* D = (const float*)d_in[2];
    float* out = (float*)d_out;

    const int B = in_sizes[0] / (NV * 2);   // 2
    dim3 grid(NFP / GROUPS, B);             // (520, 2) = 1040 blocks
    ddsl_spec_kernel<<<grid, BLOCK>>>(V, E, D, out);
}